// round 4
// baseline (speedup 1.0000x reference)
#include <cuda_runtime.h>
#include <cuda_bf16.h>

// AWingLoss with dilated-target mask, single fused kernel.
// (B,C,H,W)=(32,68,128,128) fp32. W=H=128.
// Mask: 3x3 grey dilation, symmetric pad=1 (== edge clamp), >0.2 ? 11 : 1.
//
// MUFU reduction: pow_t=2^(y-2.1), 28/(1+t), 14*ln(1+t) replaced by
// narrow-range polynomials (imm-FFMA, rt=1). Only the d^e / log1p path
// keeps MUFU (LG2, EX2, LG2). Single kernel: per-block partials +
// last-block-done final reduction (counter self-resets for graph replay).

#define NBLOCKS 1184          // 148 SMs * 8
#define NTHREADS 256
#define WARPS_PER_BLOCK 8

__device__ float        g_partials[NBLOCKS];
__device__ unsigned int g_count;   // zero-init; last block resets to 0

__device__ __forceinline__ float awing_px(float p, float y, float dil) {
    float e = 2.1f - y;

    // t = 2^(y-2.1), y in [0,1]: degree-6 Taylor of 2^y scaled by 2^-2.1
    float t = 3.59311e-05f;
    t = fmaf(t, y, 3.11016e-04f);
    t = fmaf(t, y, 2.24351e-03f);
    t = fmaf(t, y, 1.29468e-02f);
    t = fmaf(t, y, 5.60348e-02f);
    t = fmaf(t, y, 1.61682549e-01f);
    t = fmaf(t, y, 2.33258247e-01f);

    float s = t - 0.35f;   // t in [0.2333, 0.4665] -> s in [-0.117, 0.117]

    // r28 = 28/(1+t) = 28/(1.35+s), degree-4 Taylor about 1.35
    float r28 = 6.24432f;
    r28 = fmaf(r28, s, -8.42991f);
    r28 = fmaf(r28, s, 11.3803790f);
    r28 = fmaf(r28, s, -15.3635117f);
    r28 = fmaf(r28, s, 20.7407407f);

    // L14 = 14*ln(1+t) = 14*ln(1.35+s), degree-4 Taylor about 1.35
    float L14 = -1.053738f;
    L14 = fmaf(L14, s, 1.896729f);
    L14 = fmaf(L14, s, -3.8408779f);
    L14 = fmaf(L14, s, 10.3703704f);
    L14 = fmaf(L14, s, 4.20146429f);

    float A = e * t * r28;                 // 28*e*t/(1+t)
    float C = fmaf(0.5f, A, -L14);         // 0.5*A - 14*ln(1+t)

    float d = fabsf(p - y);
    // d^e via MUFU (log2/exp2); d=0 -> -inf*e -> exp2 = 0 (correct)
    float u = exp2f(e * __log2f(d));
    float lsmall = 14.0f * __logf(1.0f + u);
    float lbig   = fmaf(A, d, -C);
    float l = (d < 0.5f) ? lsmall : lbig;
    return (dil > 0.2f) ? l * 11.0f : l;
}

__global__ void __launch_bounds__(NTHREADS)
awing_kernel(const float* __restrict__ pred,
             const float* __restrict__ targ,
             int rows, float* __restrict__ out, double inv_n)
{
    const int warp = threadIdx.x >> 5;
    const int lane = threadIdx.x & 31;
    const unsigned FULL = 0xffffffffu;

    float acc = 0.0f;

    for (int r0 = blockIdx.x * WARPS_PER_BLOCK; r0 < rows;
         r0 += gridDim.x * WARPS_PER_BLOCK) {
        int r = r0 + warp;
        if (r < rows) {
            int h = r & 127;                      // H = 128
            long long base = (long long)r << 7;   // r * 128
            long long up   = (h == 0)   ? base : base - 128;
            long long dn   = (h == 127) ? base : base + 128;
            int c = lane << 2;                    // 4 px/lane, W = 128

            float4 p  = *reinterpret_cast<const float4*>(pred + base + c);
            float4 t  = *reinterpret_cast<const float4*>(targ + base + c);
            float4 tu = *reinterpret_cast<const float4*>(targ + up   + c);
            float4 td = *reinterpret_cast<const float4*>(targ + dn   + c);

            // vertical 3-max per column
            float4 v;
            v.x = fmaxf(t.x, fmaxf(tu.x, td.x));
            v.y = fmaxf(t.y, fmaxf(tu.y, td.y));
            v.z = fmaxf(t.z, fmaxf(tu.z, td.z));
            v.w = fmaxf(t.w, fmaxf(tu.w, td.w));

            // horizontal halo via shuffles (edge clamp at lane 0 / 31)
            float vL = __shfl_up_sync(FULL, v.w, 1);
            float vR = __shfl_down_sync(FULL, v.x, 1);
            if (lane == 0)  vL = v.x;
            if (lane == 31) vR = v.w;

            float d0 = fmaxf(vL,  fmaxf(v.x, v.y));
            float d1 = fmaxf(v.x, fmaxf(v.y, v.z));
            float d2 = fmaxf(v.y, fmaxf(v.z, v.w));
            float d3 = fmaxf(v.z, fmaxf(v.w, vR));

            acc += awing_px(p.x, t.x, d0);
            acc += awing_px(p.y, t.y, d1);
            acc += awing_px(p.z, t.z, d2);
            acc += awing_px(p.w, t.w, d3);
        }
    }

    // warp reduce
    #pragma unroll
    for (int o = 16; o > 0; o >>= 1)
        acc += __shfl_down_sync(FULL, acc, o);

    __shared__ float wsum[WARPS_PER_BLOCK];
    __shared__ unsigned s_last;
    if (lane == 0) wsum[warp] = acc;
    __syncthreads();

    if (threadIdx.x == 0) {
        float bsum = 0.0f;
        #pragma unroll
        for (int i = 0; i < WARPS_PER_BLOCK; i++) bsum += wsum[i];
        g_partials[blockIdx.x] = bsum;
        __threadfence();
        unsigned prev = atomicAdd(&g_count, 1u);
        s_last = (prev == (unsigned)(gridDim.x - 1)) ? 1u : 0u;
    }
    __syncthreads();

    if (s_last) {
        // last block: final reduction of all per-block partials
        volatile float* vp = g_partials;
        double s = 0.0;
        for (int i = threadIdx.x; i < NBLOCKS; i += NTHREADS)
            s += (double)vp[i];

        __shared__ double dred[NTHREADS];
        dred[threadIdx.x] = s;
        __syncthreads();
        #pragma unroll
        for (int stride = NTHREADS / 2; stride > 0; stride >>= 1) {
            if (threadIdx.x < stride)
                dred[threadIdx.x] += dred[threadIdx.x + stride];
            __syncthreads();
        }
        if (threadIdx.x == 0) {
            out[0] = (float)(dred[0] * inv_n);
            g_count = 0;    // reset for next graph replay
        }
    }
}

extern "C" void kernel_launch(void* const* d_in, const int* in_sizes, int n_in,
                              void* d_out, int out_size) {
    const float* pred = (const float*)d_in[0];
    const float* targ = (const float*)d_in[1];
    float* out = (float*)d_out;

    int n = in_sizes[0];          // B*C*H*W
    int rows = n >> 7;            // n / 128 (W = 128)
    double inv_n = 1.0 / (double)n;

    awing_kernel<<<NBLOCKS, NTHREADS>>>(pred, targ, rows, out, inv_n);
}

// round 9
// speedup vs baseline: 1.1166x; 1.1166x over previous
#include <cuda_runtime.h>
#include <cuda_bf16.h>

// AWingLoss + dilated-target mask, single fused kernel, packed-f32x2 math.
// (B,C,H,W)=(32,68,128,128) fp32. W=H=128.
// Mask: 3x3 grey dilation, symmetric pad=1 (== edge clamp), >0.2 ? 11 : 1.
//
// All y-only math (t=2^(y-2.1) poly, 28/(1+t) poly, -14*ln(1+t) poly, A, C)
// runs in packed f32x2 (FFMA2/FADD2/FMUL2) -> ~half the fp32 issue count.
// Scalar remainder: d, the d^e/log1p MUFU chain, selects, accumulate.
// Grid stride 1184*8=9472 rows == 0 mod 128 -> h invariant per warp,
// addresses are pure pointer bumps.

#define NBLOCKS 1184          // 148 SMs * 8
#define NTHREADS 256
#define WARPS_PER_BLOCK 8
#define ROW_STRIDE (NBLOCKS * WARPS_PER_BLOCK)   // 9472 = 74*128

__device__ float        g_partials[NBLOCKS];
__device__ unsigned int g_count;   // zero-init; last block resets to 0

typedef unsigned long long u64;

__device__ __forceinline__ u64 pk(float lo, float hi) {
    u64 r; asm("mov.b64 %0, {%1, %2};" : "=l"(r) : "f"(lo), "f"(hi)); return r;
}
__device__ __forceinline__ u64 pk2(float c) { return pk(c, c); }
__device__ __forceinline__ void upk(float& lo, float& hi, u64 v) {
    asm("mov.b64 {%0, %1}, %2;" : "=f"(lo), "=f"(hi) : "l"(v));
}
__device__ __forceinline__ u64 f2fma(u64 a, u64 b, u64 c) {
    u64 d; asm("fma.rn.f32x2 %0, %1, %2, %3;" : "=l"(d) : "l"(a), "l"(b), "l"(c)); return d;
}
__device__ __forceinline__ u64 f2mul(u64 a, u64 b) {
    u64 d; asm("mul.rn.f32x2 %0, %1, %2;" : "=l"(d) : "l"(a), "l"(b)); return d;
}
__device__ __forceinline__ u64 f2add(u64 a, u64 b) {
    u64 d; asm("add.rn.f32x2 %0, %1, %2;" : "=l"(d) : "l"(a), "l"(b)); return d;
}

// Scalar tail: needs A, C, e (from packed stage), pred, targ, dilation.
__device__ __forceinline__ float loss_scalar(float p, float y, float A, float C,
                                             float e, float dil) {
    float d  = fabsf(p - y);
    // d^e via MUFU; d=0 -> log2=-inf -> exp2=0 (correct)
    float u  = exp2f(e * __log2f(d));
    float ls = 9.70406053f * __log2f(1.0f + u);   // 14*ln(1+u)
    float lb = fmaf(A, d, -C);
    float l  = (d < 0.5f) ? ls : lb;
    return (dil > 0.2f) ? 11.0f * l : l;
}

__global__ void __launch_bounds__(NTHREADS)
awing_kernel(const float* __restrict__ pred,
             const float* __restrict__ targ,
             int rows, float* __restrict__ out, double inv_n)
{
    const int warp = threadIdx.x >> 5;
    const int lane = threadIdx.x & 31;
    const unsigned FULL = 0xffffffffu;

    // Packed constants (loop-invariant, live in registers).
    // t = 2^(y-2.1), y in [0,1]: degree-6 Taylor (verified coefficients).
    const u64 C6 = pk2(3.59311e-05f),  C5 = pk2(3.11016e-04f),
              C4 = pk2(2.24351e-03f),  C3 = pk2(1.29468e-02f),
              C2 = pk2(5.60348e-02f),  C1 = pk2(1.61682549e-01f),
              C0 = pk2(2.33258247e-01f),
              SM = pk2(-0.35f),
    // r28 = 28/(1+t) about t=0.35 (degree 4)
              B4 = pk2(6.24432f),      B3 = pk2(-8.42991f),
              B2 = pk2(11.3803790f),   B1 = pk2(-15.3635117f),
              B0 = pk2(20.7407407f),
    // N* = negated L14 coeffs -> evaluates -14*ln(1+t) directly
              N4 = pk2(1.053738f),     N3 = pk2(-1.896729f),
              N2 = pk2(3.8408779f),    N1 = pk2(-10.3703704f),
              N0 = pk2(-4.20146429f),
              NEG1 = pk2(-1.0f), K21 = pk2(2.1f), HALF = pk2(0.5f);

    const int r0 = blockIdx.x * WARPS_PER_BLOCK + warp;   // [0, 9472)
    const int h  = r0 & 127;                               // invariant: 9472 % 128 == 0
    const int upOff = (h == 0)   ? 0 : -32;                // float4 units
    const int dnOff = (h == 127) ? 0 :  32;
    const int STRIDE4 = ROW_STRIDE * 32;                   // float4 units per sweep

    const float4* prow = reinterpret_cast<const float4*>(pred) + r0 * 32 + lane;
    const float4* trow = reinterpret_cast<const float4*>(targ) + r0 * 32 + lane;

    float acc = 0.0f;

    for (int r = r0; r < rows; r += ROW_STRIDE) {
        float4 p  = *prow;
        float4 t  = *trow;
        float4 tu = trow[upOff];
        float4 td = trow[dnOff];

        // vertical 3-max per column (FMNMX, alu pipe)
        float4 v;
        v.x = fmaxf(t.x, fmaxf(tu.x, td.x));
        v.y = fmaxf(t.y, fmaxf(tu.y, td.y));
        v.z = fmaxf(t.z, fmaxf(tu.z, td.z));
        v.w = fmaxf(t.w, fmaxf(tu.w, td.w));

        // horizontal halo via shuffles (edge clamp at lane 0 / 31)
        float vL = __shfl_up_sync(FULL, v.w, 1);
        float vR = __shfl_down_sync(FULL, v.x, 1);
        if (lane == 0)  vL = v.x;
        if (lane == 31) vR = v.w;

        float m01 = fmaxf(v.x, v.y);
        float m23 = fmaxf(v.z, v.w);
        float d0 = fmaxf(vL,  m01);
        float d1 = fmaxf(m01, v.z);
        float d2 = fmaxf(v.y, m23);
        float d3 = fmaxf(m23, vR);

        // ---- packed y-math, pair (t.x, t.y) ----
        u64 yA = pk(t.x, t.y);
        u64 eA = f2fma(yA, NEG1, K21);                 // e = 2.1 - y
        u64 tA = f2fma(C6, yA, C5);
        tA = f2fma(tA, yA, C4);  tA = f2fma(tA, yA, C3);
        tA = f2fma(tA, yA, C2);  tA = f2fma(tA, yA, C1);
        tA = f2fma(tA, yA, C0);                        // t = 2^(y-2.1)
        u64 sA = f2add(tA, SM);
        u64 rA = f2fma(B4, sA, B3);
        rA = f2fma(rA, sA, B2);  rA = f2fma(rA, sA, B1);
        rA = f2fma(rA, sA, B0);                        // 28/(1+t)
        u64 gA = f2fma(N4, sA, N3);
        gA = f2fma(gA, sA, N2);  gA = f2fma(gA, sA, N1);
        gA = f2fma(gA, sA, N0);                        // -14*ln(1+t)
        u64 AA = f2mul(f2mul(eA, tA), rA);             // A
        u64 CA = f2fma(AA, HALF, gA);                  // C = 0.5A - L14

        // ---- packed y-math, pair (t.z, t.w) ----
        u64 yB = pk(t.z, t.w);
        u64 eB = f2fma(yB, NEG1, K21);
        u64 tB = f2fma(C6, yB, C5);
        tB = f2fma(tB, yB, C4);  tB = f2fma(tB, yB, C3);
        tB = f2fma(tB, yB, C2);  tB = f2fma(tB, yB, C1);
        tB = f2fma(tB, yB, C0);
        u64 sB = f2add(tB, SM);
        u64 rB = f2fma(B4, sB, B3);
        rB = f2fma(rB, sB, B2);  rB = f2fma(rB, sB, B1);
        rB = f2fma(rB, sB, B0);
        u64 gB = f2fma(N4, sB, N3);
        gB = f2fma(gB, sB, N2);  gB = f2fma(gB, sB, N1);
        gB = f2fma(gB, sB, N0);
        u64 AB = f2mul(f2mul(eB, tB), rB);
        u64 CB = f2fma(AB, HALF, gB);

        float A0, A1, A2, A3, Cc0, Cc1, Cc2, Cc3, e0, e1, e2, e3;
        upk(A0, A1, AA);  upk(A2, A3, AB);
        upk(Cc0, Cc1, CA); upk(Cc2, Cc3, CB);
        upk(e0, e1, eA);  upk(e2, e3, eB);

        acc += loss_scalar(p.x, t.x, A0, Cc0, e0, d0);
        acc += loss_scalar(p.y, t.y, A1, Cc1, e1, d1);
        acc += loss_scalar(p.z, t.z, A2, Cc2, e2, d2);
        acc += loss_scalar(p.w, t.w, A3, Cc3, e3, d3);

        prow += STRIDE4;
        trow += STRIDE4;
    }

    // warp reduce
    #pragma unroll
    for (int o = 16; o > 0; o >>= 1)
        acc += __shfl_down_sync(FULL, acc, o);

    __shared__ float wsum[WARPS_PER_BLOCK];
    __shared__ unsigned s_last;
    if (lane == 0) wsum[warp] = acc;
    __syncthreads();

    if (threadIdx.x == 0) {
        float bsum = 0.0f;
        #pragma unroll
        for (int i = 0; i < WARPS_PER_BLOCK; i++) bsum += wsum[i];
        g_partials[blockIdx.x] = bsum;
        __threadfence();
        unsigned prev = atomicAdd(&g_count, 1u);
        s_last = (prev == (unsigned)(gridDim.x - 1)) ? 1u : 0u;
    }
    __syncthreads();

    if (s_last) {
        volatile float* vp = g_partials;
        double s = 0.0;
        for (int i = threadIdx.x; i < NBLOCKS; i += NTHREADS)
            s += (double)vp[i];

        __shared__ double dred[NTHREADS];
        dred[threadIdx.x] = s;
        __syncthreads();
        #pragma unroll
        for (int stride = NTHREADS / 2; stride > 0; stride >>= 1) {
            if (threadIdx.x < stride)
                dred[threadIdx.x] += dred[threadIdx.x + stride];
            __syncthreads();
        }
        if (threadIdx.x == 0) {
            out[0] = (float)(dred[0] * inv_n);
            g_count = 0;    // reset for next graph replay
        }
    }
}

extern "C" void kernel_launch(void* const* d_in, const int* in_sizes, int n_in,
                              void* d_out, int out_size) {
    const float* pred = (const float*)d_in[0];
    const float* targ = (const float*)d_in[1];
    float* out = (float*)d_out;

    int n = in_sizes[0];          // B*C*H*W
    int rows = n >> 7;            // n / 128 (W = 128)
    double inv_n = 1.0 / (double)n;

    awing_kernel<<<NBLOCKS, NTHREADS>>>(pred, targ, rows, out, inv_n);
}

// round 16
// speedup vs baseline: 1.1205x; 1.0035x over previous
#include <cuda_runtime.h>
#include <cuda_bf16.h>

// AWingLoss + dilated-target mask, single fused kernel, packed-f32x2 math.
// (B,C,H,W)=(32,68,128,128) fp32. W=H=128.
// Mask: 3x3 grey dilation, symmetric pad=1 (== edge clamp), >0.2 ? 11 : 1.
//
// Identical inner loop to the verified R9 kernel (64.2us, rel_err 4.8e-7).
// Single change: one-wave grid 888 = 148 SMs x 6 blocks (regs 40 -> 6/SM),
// which requires recomputing h/upOff/dnOff per iteration (stride 7104 is
// not a multiple of 128). __launch_bounds__(256,6) pins 6 blocks/SM.

#define NBLOCKS 888           // 148 SMs * 6 blocks (one wave at regs<=42)
#define NTHREADS 256
#define WARPS_PER_BLOCK 8
#define ROW_STRIDE (NBLOCKS * WARPS_PER_BLOCK)   // 7104

__device__ float        g_partials[NBLOCKS];
__device__ unsigned int g_count;   // zero-init; last block resets to 0

typedef unsigned long long u64;

__device__ __forceinline__ u64 pk(float lo, float hi) {
    u64 r; asm("mov.b64 %0, {%1, %2};" : "=l"(r) : "f"(lo), "f"(hi)); return r;
}
__device__ __forceinline__ u64 pk2(float c) { return pk(c, c); }
__device__ __forceinline__ void upk(float& lo, float& hi, u64 v) {
    asm("mov.b64 {%0, %1}, %2;" : "=f"(lo), "=f"(hi) : "l"(v));
}
__device__ __forceinline__ u64 f2fma(u64 a, u64 b, u64 c) {
    u64 d; asm("fma.rn.f32x2 %0, %1, %2, %3;" : "=l"(d) : "l"(a), "l"(b), "l"(c)); return d;
}
__device__ __forceinline__ u64 f2mul(u64 a, u64 b) {
    u64 d; asm("mul.rn.f32x2 %0, %1, %2;" : "=l"(d) : "l"(a), "l"(b)); return d;
}
__device__ __forceinline__ u64 f2add(u64 a, u64 b) {
    u64 d; asm("add.rn.f32x2 %0, %1, %2;" : "=l"(d) : "l"(a), "l"(b)); return d;
}

// Scalar tail: needs A, C, e (from packed stage), pred, targ, dilation.
__device__ __forceinline__ float loss_scalar(float p, float y, float A, float C,
                                             float e, float dil) {
    float d  = fabsf(p - y);
    // d^e via MUFU; d=0 -> log2=-inf -> exp2=0 (correct)
    float u  = exp2f(e * __log2f(d));
    float ls = 9.70406053f * __log2f(1.0f + u);   // 14*ln(1+u)
    float lb = fmaf(A, d, -C);
    float l  = (d < 0.5f) ? ls : lb;
    return (dil > 0.2f) ? 11.0f * l : l;
}

__global__ void __launch_bounds__(NTHREADS, 6)
awing_kernel(const float* __restrict__ pred,
             const float* __restrict__ targ,
             int rows, float* __restrict__ out, double inv_n)
{
    const int warp = threadIdx.x >> 5;
    const int lane = threadIdx.x & 31;
    const unsigned FULL = 0xffffffffu;

    // Packed constants (loop-invariant, live in registers).
    // t = 2^(y-2.1), y in [0,1]: degree-6 Taylor (verified coefficients).
    const u64 C6 = pk2(3.59311e-05f),  C5 = pk2(3.11016e-04f),
              C4 = pk2(2.24351e-03f),  C3 = pk2(1.29468e-02f),
              C2 = pk2(5.60348e-02f),  C1 = pk2(1.61682549e-01f),
              C0 = pk2(2.33258247e-01f),
              SM = pk2(-0.35f),
    // r28 = 28/(1+t) about t=0.35 (degree 4)
              B4 = pk2(6.24432f),      B3 = pk2(-8.42991f),
              B2 = pk2(11.3803790f),   B1 = pk2(-15.3635117f),
              B0 = pk2(20.7407407f),
    // N* = negated L14 coeffs -> evaluates -14*ln(1+t) directly
              N4 = pk2(1.053738f),     N3 = pk2(-1.896729f),
              N2 = pk2(3.8408779f),    N1 = pk2(-10.3703704f),
              N0 = pk2(-4.20146429f),
              NEG1 = pk2(-1.0f), K21 = pk2(2.1f), HALF = pk2(0.5f);

    const int r0 = blockIdx.x * WARPS_PER_BLOCK + warp;   // [0, 7104)
    const int STRIDE4 = ROW_STRIDE * 32;                   // float4 units per sweep

    const float4* prow = reinterpret_cast<const float4*>(pred) + r0 * 32 + lane;
    const float4* trow = reinterpret_cast<const float4*>(targ) + r0 * 32 + lane;

    float acc = 0.0f;

    for (int r = r0; r < rows; r += ROW_STRIDE) {
        // h varies per sweep (7104 % 128 != 0): recompute halo offsets.
        const int h = r & 127;
        const int upOff = (h == 0)   ? 0 : -32;            // float4 units
        const int dnOff = (h == 127) ? 0 :  32;

        float4 p  = *prow;
        float4 t  = *trow;
        float4 tu = trow[upOff];
        float4 td = trow[dnOff];

        // vertical 3-max per column (FMNMX, alu pipe)
        float4 v;
        v.x = fmaxf(t.x, fmaxf(tu.x, td.x));
        v.y = fmaxf(t.y, fmaxf(tu.y, td.y));
        v.z = fmaxf(t.z, fmaxf(tu.z, td.z));
        v.w = fmaxf(t.w, fmaxf(tu.w, td.w));

        // horizontal halo via shuffles (edge clamp at lane 0 / 31)
        float vL = __shfl_up_sync(FULL, v.w, 1);
        float vR = __shfl_down_sync(FULL, v.x, 1);
        if (lane == 0)  vL = v.x;
        if (lane == 31) vR = v.w;

        float m01 = fmaxf(v.x, v.y);
        float m23 = fmaxf(v.z, v.w);
        float d0 = fmaxf(vL,  m01);
        float d1 = fmaxf(m01, v.z);
        float d2 = fmaxf(v.y, m23);
        float d3 = fmaxf(m23, vR);

        // ---- packed y-math, pair (t.x, t.y) ----
        u64 yA = pk(t.x, t.y);
        u64 eA = f2fma(yA, NEG1, K21);                 // e = 2.1 - y
        u64 tA = f2fma(C6, yA, C5);
        tA = f2fma(tA, yA, C4);  tA = f2fma(tA, yA, C3);
        tA = f2fma(tA, yA, C2);  tA = f2fma(tA, yA, C1);
        tA = f2fma(tA, yA, C0);                        // t = 2^(y-2.1)
        u64 sA = f2add(tA, SM);
        u64 rA = f2fma(B4, sA, B3);
        rA = f2fma(rA, sA, B2);  rA = f2fma(rA, sA, B1);
        rA = f2fma(rA, sA, B0);                        // 28/(1+t)
        u64 gA = f2fma(N4, sA, N3);
        gA = f2fma(gA, sA, N2);  gA = f2fma(gA, sA, N1);
        gA = f2fma(gA, sA, N0);                        // -14*ln(1+t)
        u64 AA = f2mul(f2mul(eA, tA), rA);             // A
        u64 CA = f2fma(AA, HALF, gA);                  // C = 0.5A - L14

        // ---- packed y-math, pair (t.z, t.w) ----
        u64 yB = pk(t.z, t.w);
        u64 eB = f2fma(yB, NEG1, K21);
        u64 tB = f2fma(C6, yB, C5);
        tB = f2fma(tB, yB, C4);  tB = f2fma(tB, yB, C3);
        tB = f2fma(tB, yB, C2);  tB = f2fma(tB, yB, C1);
        tB = f2fma(tB, yB, C0);
        u64 sB = f2add(tB, SM);
        u64 rB = f2fma(B4, sB, B3);
        rB = f2fma(rB, sB, B2);  rB = f2fma(rB, sB, B1);
        rB = f2fma(rB, sB, B0);
        u64 gB = f2fma(N4, sB, N3);
        gB = f2fma(gB, sB, N2);  gB = f2fma(gB, sB, N1);
        gB = f2fma(gB, sB, N0);
        u64 AB = f2mul(f2mul(eB, tB), rB);
        u64 CB = f2fma(AB, HALF, gB);

        float A0, A1, A2, A3, Cc0, Cc1, Cc2, Cc3, e0, e1, e2, e3;
        upk(A0, A1, AA);  upk(A2, A3, AB);
        upk(Cc0, Cc1, CA); upk(Cc2, Cc3, CB);
        upk(e0, e1, eA);  upk(e2, e3, eB);

        acc += loss_scalar(p.x, t.x, A0, Cc0, e0, d0);
        acc += loss_scalar(p.y, t.y, A1, Cc1, e1, d1);
        acc += loss_scalar(p.z, t.z, A2, Cc2, e2, d2);
        acc += loss_scalar(p.w, t.w, A3, Cc3, e3, d3);

        prow += STRIDE4;
        trow += STRIDE4;
    }

    // warp reduce
    #pragma unroll
    for (int o = 16; o > 0; o >>= 1)
        acc += __shfl_down_sync(FULL, acc, o);

    __shared__ float wsum[WARPS_PER_BLOCK];
    __shared__ unsigned s_last;
    if (lane == 0) wsum[warp] = acc;
    __syncthreads();

    if (threadIdx.x == 0) {
        float bsum = 0.0f;
        #pragma unroll
        for (int i = 0; i < WARPS_PER_BLOCK; i++) bsum += wsum[i];
        g_partials[blockIdx.x] = bsum;
        __threadfence();
        unsigned prev = atomicAdd(&g_count, 1u);
        s_last = (prev == (unsigned)(gridDim.x - 1)) ? 1u : 0u;
    }
    __syncthreads();

    if (s_last) {
        // last block: final reduction of all per-block partials
        volatile float* vp = g_partials;
        double s = 0.0;
        for (int i = threadIdx.x; i < NBLOCKS; i += NTHREADS)
            s += (double)vp[i];

        __shared__ double dred[NTHREADS];
        dred[threadIdx.x] = s;
        __syncthreads();
        #pragma unroll
        for (int stride = NTHREADS / 2; stride > 0; stride >>= 1) {
            if (threadIdx.x < stride)
                dred[threadIdx.x] += dred[threadIdx.x + stride];
            __syncthreads();
        }
        if (threadIdx.x == 0) {
            out[0] = (float)(dred[0] * inv_n);
            g_count = 0;    // reset for next graph replay
        }
    }
}

extern "C" void kernel_launch(void* const* d_in, const int* in_sizes, int n_in,
                              void* d_out, int out_size) {
    const float* pred = (const float*)d_in[0];
    const float* targ = (const float*)d_in[1];
    float* out = (float*)d_out;

    int n = in_sizes[0];          // B*C*H*W
    int rows = n >> 7;            // n / 128 (W = 128)
    double inv_n = 1.0 / (double)n;

    awing_kernel<<<NBLOCKS, NTHREADS>>>(pred, targ, rows, out, inv_n);
}